// round 11
// baseline (speedup 1.0000x reference)
#include <cuda_runtime.h>
#include <cuda_bf16.h>
#include <math.h>

// Problem constants (fixed by reference)
#define B_      16
#define T_      8192
#define D_      512
#define H_      8
#define HD_     64
#define K_      4
#define TR_     8                 // rows per tile
#define TB_     (T_/TR_)          // 1024 tiles per batch
#define NTHR_   256
#define NBUF_   3

// One balanced wave at 3 CTAs/SM on 152 SMs: 456 = 8x29 + 8x28
#define G_      456
#define GB_HI_  29
#define GB_LO_  28
#define C_HI_   (8*GB_HI_)        // 232

// Per-warp buffer: 8 rows x 68 floats (64 data + 4 pad) + 8 mask ints.
#define WSTR_    68
#define WBUF_F   (TR_*WSTR_ + 8)          // 552 floats
#define SM_WARPS_F (H_*NBUF_*WBUF_F)      // 13248 floats
#define QSTR_    516                      // padded q row: k*516 mod 32 banks distinct
#define SM_Q_F   (K_*QSTR_)               // 2064
#define SM_P_F   (H_*TR_*K_)              // 256
#define SMEM_BYTES ((SM_WARPS_F + SM_Q_F + SM_P_F)*4)   // 62272 B -> 3 CTAs/SM

// ---------------- device scratch (no allocations allowed) ----------------
__device__ __align__(16) float g_pool[B_*K_*D_];     // atomic accumulators
__device__ __align__(16) float g_lsum[B_*K_*H_];     // atomic denominators

// ---------------- packed fp32x2 FMA (Blackwell) ----------------
union F2U { float2 f; unsigned long long u; };
__device__ __forceinline__ float2 ffma2(float2 a, float2 b, float2 c) {
    F2U A, Bv, C, Dv;
    A.f = a; Bv.f = b; C.f = c;
    asm("fma.rn.f32x2 %0, %1, %2, %3;" : "=l"(Dv.u) : "l"(A.u), "l"(Bv.u), "l"(C.u));
    return Dv.f;
}

#define CP_COMMIT() asm volatile("cp.async.commit_group;")
#define CP_WAIT1()  asm volatile("cp.async.wait_group 1;")
#define CP_WAIT0()  asm volatile("cp.async.wait_group 0;")

__device__ __forceinline__ void cp16(float* dst_sh, const void* src) {
    unsigned d = (unsigned)__cvta_generic_to_shared(dst_sh);
    asm volatile("cp.async.cg.shared.global [%0], [%1], 16;" :: "r"(d), "l"(src));
}

// Per-warp: copy this head's 64-float slice of 8 rows (+ 8 mask ints).
__device__ __forceinline__ void issue_wtile(const float* __restrict__ src,
                                            float* __restrict__ dst,
                                            const int* __restrict__ msrc,
                                            int lane)
{
    #pragma unroll
    for (int i = 0; i < 4; i++) {
        int cchunk = lane + 32 * i;          // 0..127
        int row = cchunk >> 4;               // 0..7
        int ch  = cchunk & 15;               // 0..15
        cp16(dst + row * WSTR_ + ch * 4, src + (long)row * D_ + ch * 4);
    }
    if (lane < 2)
        cp16(dst + TR_ * WSTR_ + lane * 4, msrc + lane * 4);
}

// ======================================================================
// Kernel 0: zero the atomic accumulators
// ======================================================================
__global__ void zero_k()
{
    int i = blockIdx.x * 256 + threadIdx.x;
    if (i < B_*K_*D_) g_pool[i] = 0.f;
    if (i < B_*K_*H_) g_lsum[i] = 0.f;
}

// ======================================================================
// Kernel 1: warp-autonomous attention pooling, fixed softmax shift (m=0).
// lane = (row, k). q in padded SMEM (bank-clean quad reads). 3 CTAs/SM.
// ======================================================================
__global__ void __launch_bounds__(NTHR_, 3)
attn_main(const float* __restrict__ x, const int* __restrict__ mask,
          const float* __restrict__ queries)
{
    extern __shared__ float sm[];
    float* q_sh = sm + SM_WARPS_F;             // [K][516]
    float* p_sh = q_sh + SM_Q_F;               // [H][8][K]

    const int c    = blockIdx.x;
    const int tid  = threadIdx.x;
    const int w    = tid >> 5;                 // warp == head
    const int lane = tid & 31;
    const int row  = lane >> 2;                // 0..7
    const int k_ln = lane & 3;                 // this lane's query index

    int b, j, Gb;
    if (c < C_HI_) { b = c / GB_HI_; j = c % GB_HI_; Gb = GB_HI_; }
    else { int c2 = c - C_HI_; b = 8 + c2 / GB_LO_; j = c2 % GB_LO_; Gb = GB_LO_; }
    const int tstart = (j * TB_) / Gb;
    const int ntiles = ((j + 1) * TB_) / Gb - tstart;   // ~35-36, always >= 3

    const float* xw = x + ((long)b * T_ + (long)tstart * TR_) * D_ + w * HD_;
    const int*   mw = mask + (long)b * T_ + tstart * TR_;
    float* wb  = sm + w * NBUF_ * WBUF_F;      // private buffers
    float* p_w = p_sh + w * TR_ * K_;

    // queries -> padded shared rows (cooperative, once)
    #pragma unroll
    for (int i = tid; i < K_ * D_ / 4; i += NTHR_) {
        int k = i >> 7, cc = i & 127;
        *reinterpret_cast<float4*>(q_sh + k * QSTR_ + cc * 4) =
            *reinterpret_cast<const float4*>(queries + (long)k * D_ + cc * 4);
    }

    float  l = 0.f;
    float2 acc[K_];
    #pragma unroll
    for (int k = 0; k < K_; k++) acc[k] = make_float2(0.f, 0.f);

    // prologue: 2 tiles in flight
    issue_wtile(xw, wb, mw, lane);
    CP_COMMIT();
    issue_wtile(xw + (long)TR_ * D_, wb + WBUF_F, mw + TR_, lane);
    CP_COMMIT();

    __syncthreads();                           // q_sh visible (only block sync)

    const float* qh = q_sh + k_ln * QSTR_ + w * HD_;

    for (int tl = 0; tl < ntiles; tl++) {
        if (tl + 1 < ntiles) CP_WAIT1(); else CP_WAIT0();
        __syncwarp();

        float* tile = wb + (tl % NBUF_) * WBUF_F;
        const int* msk = (const int*)(tile + TR_ * WSTR_);

        // ---- phase 1: 64-dim dot, 4 independent partial sums ----
        float2 s0 = make_float2(0.f, 0.f), s1 = make_float2(0.f, 0.f);
        float2 s2 = make_float2(0.f, 0.f), s3 = make_float2(0.f, 0.f);
        const float* vrow = tile + row * WSTR_;
        #pragma unroll
        for (int g = 0; g < 4; g++) {
            float4 va = *reinterpret_cast<const float4*>(vrow + (g*4+0) * 4);
            float4 vb = *reinterpret_cast<const float4*>(vrow + (g*4+1) * 4);
            float4 vc = *reinterpret_cast<const float4*>(vrow + (g*4+2) * 4);
            float4 vd = *reinterpret_cast<const float4*>(vrow + (g*4+3) * 4);
            float4 qa = *reinterpret_cast<const float4*>(qh + (g*4+0) * 4);
            float4 qb = *reinterpret_cast<const float4*>(qh + (g*4+1) * 4);
            float4 qc = *reinterpret_cast<const float4*>(qh + (g*4+2) * 4);
            float4 qd = *reinterpret_cast<const float4*>(qh + (g*4+3) * 4);
            s0 = ffma2(make_float2(va.x, va.y), make_float2(qa.x, qa.y), s0);
            s1 = ffma2(make_float2(va.z, va.w), make_float2(qa.z, qa.w), s1);
            s2 = ffma2(make_float2(vb.x, vb.y), make_float2(qb.x, qb.y), s2);
            s3 = ffma2(make_float2(vb.z, vb.w), make_float2(qb.z, qb.w), s3);
            s0 = ffma2(make_float2(vc.x, vc.y), make_float2(qc.x, qc.y), s0);
            s1 = ffma2(make_float2(vc.z, vc.w), make_float2(qc.z, qc.w), s1);
            s2 = ffma2(make_float2(vd.x, vd.y), make_float2(qd.x, qd.y), s2);
            s3 = ffma2(make_float2(vd.z, vd.w), make_float2(qd.z, qd.w), s3);
        }
        float v = ((s0.x + s1.x) + (s2.x + s3.x)) + ((s0.y + s1.y) + (s2.y + s3.y));
        float p = (msk[row] == 0) ? 0.f : __expf(v * 0.125f);
        l += p;
        p_w[lane] = p;                         // [row][k] contiguous
        __syncwarp();

        // ---- phase 2: lane owns d = {2*lane, 2*lane+1} of this head ----
        const float* base2 = tile + 2 * lane;
        #pragma unroll
        for (int t = 0; t < TR_; t++) {
            float2 v2 = *reinterpret_cast<const float2*>(base2 + t * WSTR_);
            float4 p4 = *reinterpret_cast<const float4*>(p_w + t * K_);
            acc[0] = ffma2(v2, make_float2(p4.x, p4.x), acc[0]);
            acc[1] = ffma2(v2, make_float2(p4.y, p4.y), acc[1]);
            acc[2] = ffma2(v2, make_float2(p4.z, p4.z), acc[2]);
            acc[3] = ffma2(v2, make_float2(p4.w, p4.w), acc[3]);
        }
        __syncwarp();                          // lanes done reading buffer & p_w

        if (tl + 2 < ntiles) {
            issue_wtile(xw + (long)(tl + 2) * TR_ * D_,
                        wb + ((tl + 2) % NBUF_) * WBUF_F,
                        mw + (tl + 2) * TR_, lane);
            CP_COMMIT();
        }
    }

    // ---- reduce l over rows (lanes sharing k = lane&3) ----
    l += __shfl_xor_sync(0xffffffffu, l, 4);
    l += __shfl_xor_sync(0xffffffffu, l, 8);
    l += __shfl_xor_sync(0xffffffffu, l, 16);

    // ---- atomic tail: plain sums across CTAs (m = 0 everywhere) ----
    if (lane < K_)
        atomicAdd(&g_lsum[((long)b * K_ + lane) * H_ + w], l);
    #pragma unroll
    for (int k = 0; k < K_; k++) {
        float* dst = &g_pool[((long)b * K_ + k) * D_ + w * HD_ + 2 * lane];
        atomicAdd(dst,     acc[k].x);
        atomicAdd(dst + 1, acc[k].y);
    }
}

// ======================================================================
// Kernel 2: normalize pooled rows + linear projection.
// ======================================================================
__global__ void __launch_bounds__(256)
epi_k(const float* __restrict__ w_out, const float* __restrict__ b_out,
      float* __restrict__ out)
{
    __shared__ __align__(16) float ps[8][D_];
    __shared__ float slt[8][H_];
    const int rg  = blockIdx.x;             // rows rg*8..rg*8+7  (row = b*K + k)
    const int jg  = blockIdx.y;
    const int tid = threadIdx.x;

    if (tid < 64) {
        int r = tid >> 3, h = tid & 7;
        slt[r][h] = g_lsum[(long)(rg * 8 + r) * H_ + h];
    }
    __syncthreads();

    for (int i = tid; i < 8 * D_; i += 256) {
        int r = i >> 9, col = i & 511;
        ps[r][col] = g_pool[(long)(rg * 8 + r) * D_ + col] / slt[r][col >> 6];
    }
    __syncthreads();

    const int jl = tid & 63;
    const int rp = tid >> 6;                // rows rp*2, rp*2+1
    const int j  = jg * 64 + jl;
    const float* wr = w_out + (long)j * D_;

    float2 a0 = make_float2(0.f, 0.f), a1 = make_float2(0.f, 0.f);
    #pragma unroll 8
    for (int i4 = 0; i4 < D_/4; i4++) {
        float4 wv = *reinterpret_cast<const float4*>(wr + i4 * 4);
        float4 p0 = *reinterpret_cast<const float4*>(&ps[rp*2    ][i4*4]);
        float4 p1 = *reinterpret_cast<const float4*>(&ps[rp*2 + 1][i4*4]);
        a0 = ffma2(make_float2(wv.x, wv.y), make_float2(p0.x, p0.y), a0);
        a0 = ffma2(make_float2(wv.z, wv.w), make_float2(p0.z, p0.w), a0);
        a1 = ffma2(make_float2(wv.x, wv.y), make_float2(p1.x, p1.y), a1);
        a1 = ffma2(make_float2(wv.z, wv.w), make_float2(p1.z, p1.w), a1);
    }
    float bj = b_out[j];
    out[(long)(rg*8 + rp*2    ) * D_ + j] = bj + a0.x + a0.y;
    out[(long)(rg*8 + rp*2 + 1) * D_ + j] = bj + a1.x + a1.y;
}

// ======================================================================
extern "C" void kernel_launch(void* const* d_in, const int* in_sizes, int n_in,
                              void* d_out, int out_size)
{
    const float* x       = (const float*)d_in[0];
    const int*   mask    = (const int*)  d_in[1];
    const float* queries = (const float*)d_in[2];
    const float* w_out   = (const float*)d_in[3];
    const float* b_out   = (const float*)d_in[4];
    float* out = (float*)d_out;

    cudaFuncSetAttribute((const void*)attn_main,
                         cudaFuncAttributeMaxDynamicSharedMemorySize, SMEM_BYTES);

    zero_k<<<(B_*K_*D_ + 255) / 256, 256>>>();
    attn_main<<<G_, NTHR_, SMEM_BYTES>>>(x, mask, queries);
    epi_k<<<dim3(8, 8), 256>>>(w_out, b_out, out);
}

// round 12
// speedup vs baseline: 1.1933x; 1.1933x over previous
#include <cuda_runtime.h>
#include <cuda_bf16.h>
#include <math.h>

// Problem constants (fixed by reference)
#define B_      16
#define T_      8192
#define D_      512
#define H_      8
#define HD_     64
#define K_      4
#define TR_     8                 // rows per tile
#define TB_     (T_/TR_)          // 1024 tiles per batch
#define NTHR_   256
#define NBUF_   4

// One balanced wave at 2 CTAs/SM on 152 SMs: 304 = 16 x 19
#define GB_     19
#define G_      (B_*GB_)

// Per-warp buffer: 8 rows x 68 floats (64 data + 4 pad) + 8 mask ints.
#define WSTR_    68
#define WBUF_F   (TR_*WSTR_ + 8)          // 552 floats = 2208 B
#define SM_WARPS_F (H_*NBUF_*WBUF_F)      // 17664 floats
#define SM_P_F   (H_*2*TR_*K_)            // 512 floats (double-buffered p)
#define SMEM_BYTES ((SM_WARPS_F + SM_P_F)*4)   // 72704 B

// ---------------- device scratch (no allocations allowed) ----------------
__device__ __align__(16) float g_pool[B_*K_*D_];     // atomic accumulators
__device__ __align__(16) float g_lsum[B_*K_*H_];     // atomic denominators

// ---------------- packed fp32x2 FMA (Blackwell) ----------------
union F2U { float2 f; unsigned long long u; };
__device__ __forceinline__ float2 ffma2(float2 a, float2 b, float2 c) {
    F2U A, Bv, C, Dv;
    A.f = a; Bv.f = b; C.f = c;
    asm("fma.rn.f32x2 %0, %1, %2, %3;" : "=l"(Dv.u) : "l"(A.u), "l"(Bv.u), "l"(C.u));
    return Dv.f;
}

#define CP_COMMIT() asm volatile("cp.async.commit_group;")
#define CP_WAIT2()  asm volatile("cp.async.wait_group 2;")
#define CP_WAIT1()  asm volatile("cp.async.wait_group 1;")
#define CP_WAIT0()  asm volatile("cp.async.wait_group 0;")

__device__ __forceinline__ void cp16(float* dst_sh, const void* src) {
    unsigned d = (unsigned)__cvta_generic_to_shared(dst_sh);
    asm volatile("cp.async.cg.shared.global [%0], [%1], 16;" :: "r"(d), "l"(src));
}

// Per-warp: copy this head's 64-float slice of 8 rows (+ 8 mask ints).
__device__ __forceinline__ void issue_wtile(const float* __restrict__ src,
                                            float* __restrict__ dst,
                                            const int* __restrict__ msrc,
                                            int lane)
{
    #pragma unroll
    for (int i = 0; i < 4; i++) {
        int cchunk = lane + 32 * i;          // 0..127
        int row = cchunk >> 4;               // 0..7
        int ch  = cchunk & 15;               // 0..15
        cp16(dst + row * WSTR_ + ch * 4, src + (long)row * D_ + ch * 4);
    }
    if (lane < 2)
        cp16(dst + TR_ * WSTR_ + lane * 4, msrc + lane * 4);
}

// ======================================================================
// Kernel 1: warp-autonomous attention pooling, fixed softmax shift (m=0).
// lane = (row, k), q register-resident, NBUF=4.
// PHASE-PIPELINED: phase1(tile tl) and phase2(tile tl-1) execute in one
// straight-line region per iteration -> cross-phase ILP hides the
// dot/exp chain behind the accumulation FMA stream.
// ======================================================================
__global__ void __launch_bounds__(NTHR_, 2)
attn_main(const float* __restrict__ x, const int* __restrict__ mask,
          const float* __restrict__ queries)
{
    extern __shared__ float sm[];
    float* p_sh = sm + SM_WARPS_F;             // [H][2][8][K]

    const int c    = blockIdx.x;
    const int tid  = threadIdx.x;
    const int w    = tid >> 5;                 // warp == head
    const int lane = tid & 31;
    const int row  = lane >> 2;                // 0..7
    const int k_ln = lane & 3;                 // this lane's query index

    const int b = c / GB_;
    const int j = c % GB_;
    const int tstart = (j * TB_) / GB_;
    const int ntiles = ((j + 1) * TB_) / GB_ - tstart;   // ~53-54, always >= 4

    const float* xw = x + ((long)b * T_ + (long)tstart * TR_) * D_ + w * HD_;
    const int*   mw = mask + (long)b * T_ + tstart * TR_;
    float* wb  = sm + w * NBUF_ * WBUF_F;      // private buffers
    float* p_w = p_sh + w * 2 * TR_ * K_;      // two p slabs of 32 floats

    // ---- q -> registers: this lane's query row, this head's 64 dims ----
    float4 q[16];
    const float4* qsrc = reinterpret_cast<const float4*>(
                             queries + (long)k_ln * D_ + w * HD_);
    #pragma unroll
    for (int i = 0; i < 16; i++) q[i] = __ldg(qsrc + i);

    float  l = 0.f;
    float2 acc[K_];
    #pragma unroll
    for (int k = 0; k < K_; k++) acc[k] = make_float2(0.f, 0.f);

    // prologue: 3 tiles in flight
    #pragma unroll
    for (int i = 0; i < 3; i++) {
        issue_wtile(xw + (long)i * TR_ * D_, wb + i * WBUF_F, mw + i * TR_, lane);
        CP_COMMIT();
    }

    // ---- peel iteration 0: phase1 only ----
    {
        CP_WAIT2();
        __syncwarp();
        float* tile = wb;
        const int* msk = (const int*)(tile + TR_ * WSTR_);
        float2 s0 = make_float2(0.f,0.f), s1 = make_float2(0.f,0.f);
        float2 s2 = make_float2(0.f,0.f), s3 = make_float2(0.f,0.f);
        const float* vrow = tile + row * WSTR_;
        #pragma unroll
        for (int g = 0; g < 4; g++) {
            float4 va = *reinterpret_cast<const float4*>(vrow + (g*4+0) * 4);
            float4 vb = *reinterpret_cast<const float4*>(vrow + (g*4+1) * 4);
            float4 vc = *reinterpret_cast<const float4*>(vrow + (g*4+2) * 4);
            float4 vd = *reinterpret_cast<const float4*>(vrow + (g*4+3) * 4);
            s0 = ffma2(make_float2(va.x,va.y), make_float2(q[g*4+0].x,q[g*4+0].y), s0);
            s1 = ffma2(make_float2(va.z,va.w), make_float2(q[g*4+0].z,q[g*4+0].w), s1);
            s2 = ffma2(make_float2(vb.x,vb.y), make_float2(q[g*4+1].x,q[g*4+1].y), s2);
            s3 = ffma2(make_float2(vb.z,vb.w), make_float2(q[g*4+1].z,q[g*4+1].w), s3);
            s0 = ffma2(make_float2(vc.x,vc.y), make_float2(q[g*4+2].x,q[g*4+2].y), s0);
            s1 = ffma2(make_float2(vc.z,vc.w), make_float2(q[g*4+2].z,q[g*4+2].w), s1);
            s2 = ffma2(make_float2(vd.x,vd.y), make_float2(q[g*4+3].x,q[g*4+3].y), s2);
            s3 = ffma2(make_float2(vd.z,vd.w), make_float2(q[g*4+3].z,q[g*4+3].w), s3);
        }
        float v = ((s0.x+s1.x)+(s2.x+s3.x)) + ((s0.y+s1.y)+(s2.y+s3.y));
        float p = (msk[row] == 0) ? 0.f : __expf(v * 0.125f);
        l += p;
        p_w[lane] = p;                         // slab 0
        __syncwarp();
    }

    // ---- steady state: phase1(tl) || phase2(tl-1) ----
    for (int tl = 1; tl < ntiles; tl++) {
        if (tl + 2 < ntiles) {
            issue_wtile(xw + (long)(tl + 2) * TR_ * D_,
                        wb + ((tl + 2) & (NBUF_-1)) * WBUF_F,
                        mw + (tl + 2) * TR_, lane);
            CP_COMMIT();
        }
        int pend = ntiles - 1 - tl; if (pend > 2) pend = 2;
        if (pend == 2) CP_WAIT2(); else if (pend == 1) CP_WAIT1(); else CP_WAIT0();
        __syncwarp();

        float* tile  = wb + (tl & (NBUF_-1)) * WBUF_F;          // phase1 src
        float* tileP = wb + ((tl-1) & (NBUF_-1)) * WBUF_F;      // phase2 src
        const int* msk = (const int*)(tile + TR_ * WSTR_);
        const float* pb = p_w + ((tl-1) & 1) * TR_ * K_;        // prev p slab

        // phase 1 dot (independent accumulators)
        float2 s0 = make_float2(0.f,0.f), s1 = make_float2(0.f,0.f);
        float2 s2 = make_float2(0.f,0.f), s3 = make_float2(0.f,0.f);
        const float* vrow = tile + row * WSTR_;
        #pragma unroll
        for (int g = 0; g < 4; g++) {
            float4 va = *reinterpret_cast<const float4*>(vrow + (g*4+0) * 4);
            float4 vb = *reinterpret_cast<const float4*>(vrow + (g*4+1) * 4);
            float4 vc = *reinterpret_cast<const float4*>(vrow + (g*4+2) * 4);
            float4 vd = *reinterpret_cast<const float4*>(vrow + (g*4+3) * 4);
            s0 = ffma2(make_float2(va.x,va.y), make_float2(q[g*4+0].x,q[g*4+0].y), s0);
            s1 = ffma2(make_float2(va.z,va.w), make_float2(q[g*4+0].z,q[g*4+0].w), s1);
            s2 = ffma2(make_float2(vb.x,vb.y), make_float2(q[g*4+1].x,q[g*4+1].y), s2);
            s3 = ffma2(make_float2(vb.z,vb.w), make_float2(q[g*4+1].z,q[g*4+1].w), s3);
            s0 = ffma2(make_float2(vc.x,vc.y), make_float2(q[g*4+2].x,q[g*4+2].y), s0);
            s1 = ffma2(make_float2(vc.z,vc.w), make_float2(q[g*4+2].z,q[g*4+2].w), s1);
            s2 = ffma2(make_float2(vd.x,vd.y), make_float2(q[g*4+3].x,q[g*4+3].y), s2);
            s3 = ffma2(make_float2(vd.z,vd.w), make_float2(q[g*4+3].z,q[g*4+3].w), s3);
        }
        float v = ((s0.x+s1.x)+(s2.x+s3.x)) + ((s0.y+s1.y)+(s2.y+s3.y));
        float p = (msk[row] == 0) ? 0.f : __expf(v * 0.125f);

        // phase 2 of tile tl-1 (fully independent of the chain above;
        // ptxas interleaves these FMAs with the dot/exp latency)
        const float* base2 = tileP + 2 * lane;
        #pragma unroll
        for (int t = 0; t < TR_; t++) {
            float2 v2 = *reinterpret_cast<const float2*>(base2 + t * WSTR_);
            float4 p4 = *reinterpret_cast<const float4*>(pb + t * K_);
            acc[0] = ffma2(v2, make_float2(p4.x, p4.x), acc[0]);
            acc[1] = ffma2(v2, make_float2(p4.y, p4.y), acc[1]);
            acc[2] = ffma2(v2, make_float2(p4.z, p4.z), acc[2]);
            acc[3] = ffma2(v2, make_float2(p4.w, p4.w), acc[3]);
        }

        l += p;
        p_w[(tl & 1) * TR_ * K_ + lane] = p;
        __syncwarp();     // p visible; phase2(tl-1) done before buf reuse
    }

    // ---- epilogue: phase2 of last tile ----
    {
        int tl = ntiles - 1;
        float* tileP = wb + (tl & (NBUF_-1)) * WBUF_F;
        const float* pb = p_w + (tl & 1) * TR_ * K_;
        const float* base2 = tileP + 2 * lane;
        #pragma unroll
        for (int t = 0; t < TR_; t++) {
            float2 v2 = *reinterpret_cast<const float2*>(base2 + t * WSTR_);
            float4 p4 = *reinterpret_cast<const float4*>(pb + t * K_);
            acc[0] = ffma2(v2, make_float2(p4.x, p4.x), acc[0]);
            acc[1] = ffma2(v2, make_float2(p4.y, p4.y), acc[1]);
            acc[2] = ffma2(v2, make_float2(p4.z, p4.z), acc[2]);
            acc[3] = ffma2(v2, make_float2(p4.w, p4.w), acc[3]);
        }
    }

    // ---- reduce l over rows (lanes sharing k = lane&3) ----
    l += __shfl_xor_sync(0xffffffffu, l, 4);
    l += __shfl_xor_sync(0xffffffffu, l, 8);
    l += __shfl_xor_sync(0xffffffffu, l, 16);

    // ---- atomic tail: plain sums across CTAs (m = 0 everywhere) ----
    if (lane < K_)
        atomicAdd(&g_lsum[((long)b * K_ + lane) * H_ + w], l);
    #pragma unroll
    for (int k = 0; k < K_; k++) {
        float* dst = &g_pool[((long)b * K_ + k) * D_ + w * HD_ + 2 * lane];
        atomicAdd(dst,     acc[k].x);
        atomicAdd(dst + 1, acc[k].y);
    }
}

// ======================================================================
// Kernel 2: normalize pooled rows + linear projection.
// ======================================================================
__global__ void __launch_bounds__(256)
epi_k(const float* __restrict__ w_out, const float* __restrict__ b_out,
      float* __restrict__ out)
{
    __shared__ __align__(16) float ps[8][D_];
    __shared__ float slt[8][H_];
    const int rg  = blockIdx.x;             // rows rg*8..rg*8+7  (row = b*K + k)
    const int jg  = blockIdx.y;
    const int tid = threadIdx.x;

    if (tid < 64) {
        int r = tid >> 3, h = tid & 7;
        slt[r][h] = g_lsum[(long)(rg * 8 + r) * H_ + h];
    }
    __syncthreads();

    for (int i = tid; i < 8 * D_; i += 256) {
        int r = i >> 9, col = i & 511;
        ps[r][col] = g_pool[(long)(rg * 8 + r) * D_ + col] / slt[r][col >> 6];
    }
    __syncthreads();

    const int jl = tid & 63;
    const int rp = tid >> 6;                // rows rp*2, rp*2+1
    const int j  = jg * 64 + jl;
    const float* wr = w_out + (long)j * D_;

    float2 a0 = make_float2(0.f, 0.f), a1 = make_float2(0.f, 0.f);
    #pragma unroll 8
    for (int i4 = 0; i4 < D_/4; i4++) {
        float4 wv = *reinterpret_cast<const float4*>(wr + i4 * 4);
        float4 p0 = *reinterpret_cast<const float4*>(&ps[rp*2    ][i4*4]);
        float4 p1 = *reinterpret_cast<const float4*>(&ps[rp*2 + 1][i4*4]);
        a0 = ffma2(make_float2(wv.x, wv.y), make_float2(p0.x, p0.y), a0);
        a0 = ffma2(make_float2(wv.z, wv.w), make_float2(p0.z, p0.w), a0);
        a1 = ffma2(make_float2(wv.x, wv.y), make_float2(p1.x, p1.y), a1);
        a1 = ffma2(make_float2(wv.z, wv.w), make_float2(p1.z, p1.w), a1);
    }
    float bj = b_out[j];
    out[(long)(rg*8 + rp*2    ) * D_ + j] = bj + a0.x + a0.y;
    out[(long)(rg*8 + rp*2 + 1) * D_ + j] = bj + a1.x + a1.y;
}

// ======================================================================
extern "C" void kernel_launch(void* const* d_in, const int* in_sizes, int n_in,
                              void* d_out, int out_size)
{
    const float* x       = (const float*)d_in[0];
    const int*   mask    = (const int*)  d_in[1];
    const float* queries = (const float*)d_in[2];
    const float* w_out   = (const float*)d_in[3];
    const float* b_out   = (const float*)d_in[4];
    float* out = (float*)d_out;

    cudaFuncSetAttribute((const void*)attn_main,
                         cudaFuncAttributeMaxDynamicSharedMemorySize, SMEM_BYTES);

    // zero the atomic accumulators via graph memset nodes (replaces zero_k)
    void* p_pool = nullptr; void* p_lsum = nullptr;
    cudaGetSymbolAddress(&p_pool, g_pool);
    cudaGetSymbolAddress(&p_lsum, g_lsum);
    cudaMemsetAsync(p_pool, 0, sizeof(float) * B_ * K_ * D_);
    cudaMemsetAsync(p_lsum, 0, sizeof(float) * B_ * K_ * H_);

    attn_main<<<G_, NTHR_, SMEM_BYTES>>>(x, mask, queries);
    epi_k<<<dim3(8, 8), 256>>>(w_out, b_out, out);
}

// round 13
// speedup vs baseline: 1.5712x; 1.3167x over previous
#include <cuda_runtime.h>
#include <cuda_bf16.h>
#include <math.h>

// Problem constants (fixed by reference)
#define B_      16
#define T_      8192
#define D_      512
#define H_      8
#define HD_     64
#define K_      4
#define TR_     8                 // rows per tile
#define TB_     (T_/TR_)          // 1024 tiles per batch
#define NTHR_   256
#define NBUF_   4

// One balanced wave at 2 CTAs/SM on 152 SMs: 304 = 16 x 19
#define GB_     19
#define G_      (B_*GB_)

// Per-warp buffer: 8 rows x 68 floats (64 data + 4 pad) + 8 mask ints.
#define WSTR_    68
#define WBUF_F   (TR_*WSTR_ + 8)          // 552 floats = 2208 B
#define SM_WARPS_F (H_*NBUF_*WBUF_F)      // 17664 floats
#define SM_P_F   (H_*TR_*K_)              // 256 floats
#define SMEM_BYTES ((SM_WARPS_F + SM_P_F)*4)   // 71680 B

// ---------------- device scratch (no allocations allowed) ----------------
__device__ __align__(16) float g_pool[B_*K_*D_];     // atomic accumulators
__device__ __align__(16) float g_lsum[B_*K_*H_];     // atomic denominators

// ---------------- packed fp32x2 FMA (Blackwell) ----------------
union F2U { float2 f; unsigned long long u; };
__device__ __forceinline__ float2 ffma2(float2 a, float2 b, float2 c) {
    F2U A, Bv, C, Dv;
    A.f = a; Bv.f = b; C.f = c;
    asm("fma.rn.f32x2 %0, %1, %2, %3;" : "=l"(Dv.u) : "l"(A.u), "l"(Bv.u), "l"(C.u));
    return Dv.f;
}

#define CP_COMMIT() asm volatile("cp.async.commit_group;")
#define CP_WAIT2()  asm volatile("cp.async.wait_group 2;")
#define CP_WAIT1()  asm volatile("cp.async.wait_group 1;")
#define CP_WAIT0()  asm volatile("cp.async.wait_group 0;")

__device__ __forceinline__ void cp16(float* dst_sh, const void* src) {
    unsigned d = (unsigned)__cvta_generic_to_shared(dst_sh);
    asm volatile("cp.async.cg.shared.global [%0], [%1], 16;" :: "r"(d), "l"(src));
}

// Per-warp: copy this head's 64-float slice of 8 rows (+ 8 mask ints).
__device__ __forceinline__ void issue_wtile(const float* __restrict__ src,
                                            float* __restrict__ dst,
                                            const int* __restrict__ msrc,
                                            int lane)
{
    #pragma unroll
    for (int i = 0; i < 4; i++) {
        int cchunk = lane + 32 * i;          // 0..127
        int row = cchunk >> 4;               // 0..7
        int ch  = cchunk & 15;               // 0..15
        cp16(dst + row * WSTR_ + ch * 4, src + (long)row * D_ + ch * 4);
    }
    if (lane < 2)
        cp16(dst + TR_ * WSTR_ + lane * 4, msrc + lane * 4);
}

// ======================================================================
// Kernel 1 (R10 proven-best): warp-autonomous attention pooling,
// fixed softmax shift (m=0). lane = (row, k), q register-resident,
// NBUF=4, 4-way ILP dot product, atomic tail.
// ======================================================================
__global__ void __launch_bounds__(NTHR_, 2)
attn_main(const float* __restrict__ x, const int* __restrict__ mask,
          const float* __restrict__ queries)
{
    extern __shared__ float sm[];
    float* p_sh = sm + SM_WARPS_F;             // [H][8][K]

    const int c    = blockIdx.x;
    const int tid  = threadIdx.x;
    const int w    = tid >> 5;                 // warp == head
    const int lane = tid & 31;
    const int row  = lane >> 2;                // 0..7
    const int k_ln = lane & 3;                 // this lane's query index

    const int b = c / GB_;
    const int j = c % GB_;
    const int tstart = (j * TB_) / GB_;
    const int ntiles = ((j + 1) * TB_) / GB_ - tstart;   // ~53-54, always >= 4

    const float* xw = x + ((long)b * T_ + (long)tstart * TR_) * D_ + w * HD_;
    const int*   mw = mask + (long)b * T_ + tstart * TR_;
    float* wb  = sm + w * NBUF_ * WBUF_F;      // private buffers
    float* p_w = p_sh + w * TR_ * K_;

    // ---- q -> registers: this lane's query row, this head's 64 dims ----
    float4 q[16];
    const float4* qsrc = reinterpret_cast<const float4*>(
                             queries + (long)k_ln * D_ + w * HD_);
    #pragma unroll
    for (int i = 0; i < 16; i++) q[i] = __ldg(qsrc + i);

    float  l = 0.f;
    float2 acc[K_];
    #pragma unroll
    for (int k = 0; k < K_; k++) acc[k] = make_float2(0.f, 0.f);

    // prologue: 3 tiles in flight
    #pragma unroll
    for (int i = 0; i < 3; i++) {
        issue_wtile(xw + (long)i * TR_ * D_, wb + i * WBUF_F, mw + i * TR_, lane);
        CP_COMMIT();
    }

    for (int tl = 0; tl < ntiles; tl++) {
        int pend = ntiles - (tl + 1); if (pend > 2) pend = 2;
        if (pend == 2) CP_WAIT2(); else if (pend == 1) CP_WAIT1(); else CP_WAIT0();
        __syncwarp();

        float* tile = wb + (tl & (NBUF_-1)) * WBUF_F;
        const int* msk = (const int*)(tile + TR_ * WSTR_);

        // ---- phase 1: 64-dim dot with 4 independent partial sums ----
        float2 s0 = make_float2(0.f, 0.f), s1 = make_float2(0.f, 0.f);
        float2 s2 = make_float2(0.f, 0.f), s3 = make_float2(0.f, 0.f);
        const float* vrow = tile + row * WSTR_;
        #pragma unroll
        for (int g = 0; g < 4; g++) {          // 4 groups of 4 float4 chunks
            float4 va = *reinterpret_cast<const float4*>(vrow + (g*4+0) * 4);
            float4 vb = *reinterpret_cast<const float4*>(vrow + (g*4+1) * 4);
            float4 vc = *reinterpret_cast<const float4*>(vrow + (g*4+2) * 4);
            float4 vd = *reinterpret_cast<const float4*>(vrow + (g*4+3) * 4);
            s0 = ffma2(make_float2(va.x, va.y), make_float2(q[g*4+0].x, q[g*4+0].y), s0);
            s1 = ffma2(make_float2(va.z, va.w), make_float2(q[g*4+0].z, q[g*4+0].w), s1);
            s2 = ffma2(make_float2(vb.x, vb.y), make_float2(q[g*4+1].x, q[g*4+1].y), s2);
            s3 = ffma2(make_float2(vb.z, vb.w), make_float2(q[g*4+1].z, q[g*4+1].w), s3);
            s0 = ffma2(make_float2(vc.x, vc.y), make_float2(q[g*4+2].x, q[g*4+2].y), s0);
            s1 = ffma2(make_float2(vc.z, vc.w), make_float2(q[g*4+2].z, q[g*4+2].w), s1);
            s2 = ffma2(make_float2(vd.x, vd.y), make_float2(q[g*4+3].x, q[g*4+3].y), s2);
            s3 = ffma2(make_float2(vd.z, vd.w), make_float2(q[g*4+3].z, q[g*4+3].w), s3);
        }
        float2 t01 = make_float2(s0.x + s1.x, s0.y + s1.y);
        float2 t23 = make_float2(s2.x + s3.x, s2.y + s3.y);
        float  v   = (t01.x + t23.x) + (t01.y + t23.y);
        float p = (msk[row] == 0) ? 0.f : __expf(v * 0.125f);
        l += p;
        p_w[lane] = p;                         // [row][k] contiguous, conflict-free
        __syncwarp();

        // ---- phase 2: lane owns d = {2*lane, 2*lane+1} of this head ----
        const float* base2 = tile + 2 * lane;
        #pragma unroll
        for (int t = 0; t < TR_; t++) {
            float2 v2 = *reinterpret_cast<const float2*>(base2 + t * WSTR_);
            float4 p4 = *reinterpret_cast<const float4*>(p_w + t * K_);
            acc[0] = ffma2(v2, make_float2(p4.x, p4.x), acc[0]);
            acc[1] = ffma2(v2, make_float2(p4.y, p4.y), acc[1]);
            acc[2] = ffma2(v2, make_float2(p4.z, p4.z), acc[2]);
            acc[3] = ffma2(v2, make_float2(p4.w, p4.w), acc[3]);
        }
        __syncwarp();                          // lanes done reading buffer & p_w

        if (tl + 3 < ntiles) {
            issue_wtile(xw + (long)(tl + 3) * TR_ * D_,
                        wb + ((tl + 3) & (NBUF_-1)) * WBUF_F,
                        mw + (tl + 3) * TR_, lane);
            CP_COMMIT();
        }
    }

    // ---- reduce l over rows (lanes sharing k = lane&3) ----
    l += __shfl_xor_sync(0xffffffffu, l, 4);
    l += __shfl_xor_sync(0xffffffffu, l, 8);
    l += __shfl_xor_sync(0xffffffffu, l, 16);

    // ---- atomic tail: plain sums across CTAs (m = 0 everywhere) ----
    if (lane < K_)
        atomicAdd(&g_lsum[((long)b * K_ + lane) * H_ + w], l);
    #pragma unroll
    for (int k = 0; k < K_; k++) {
        float* dst = &g_pool[((long)b * K_ + k) * D_ + w * HD_ + 2 * lane];
        atomicAdd(dst,     acc[k].x);
        atomicAdd(dst + 1, acc[k].y);
    }
}

// ======================================================================
// Kernel 2 (REWRITTEN): normalize + linear projection, warp-per-8-outputs.
// 4096 warps (512 blocks). ALL g_pool / w_out loads lane-major coalesced
// (dot products are permutation-invariant in i). Butterfly reduce leaves
// output j's total on every lane; lanes 0..7 write the 8 outputs.
// Block's 8 warps share the same jg -> same 8 w rows (L1 reuse).
// ======================================================================
__global__ void __launch_bounds__(256)
epi_k(const float* __restrict__ w_out, const float* __restrict__ b_out,
      float* __restrict__ out)
{
    const int gw   = blockIdx.x * 8 + (threadIdx.x >> 5);   // 0..4095
    const int lane = threadIdx.x & 31;
    const int jg   = gw >> 6;               // 0..63 (shared within block)
    const int r    = gw & 63;               // pooled row = b*K + k

    // ---- load + normalize pooled row, lane-major coalesced ----
    const float4* pr = reinterpret_cast<const float4*>(g_pool + (long)r * D_);
    float4 pv[4];
    #pragma unroll
    for (int i = 0; i < 4; i++) {
        int idx = i * 32 + lane;             // float4 index; dim = idx*4
        float inv = 1.f / g_lsum[r * H_ + (idx >> 4)];
        float4 v = pr[idx];
        pv[i] = make_float4(v.x * inv, v.y * inv, v.z * inv, v.w * inv);
    }

    float my = 0.f;                          // lane j keeps output j's total
    #pragma unroll
    for (int j0 = 0; j0 < 8; j0++) {
        const float4* wr = reinterpret_cast<const float4*>(
                               w_out + (long)(jg * 8 + j0) * D_);
        float2 s = make_float2(0.f, 0.f);
        #pragma unroll
        for (int i = 0; i < 4; i++) {
            float4 wv = wr[i * 32 + lane];
            s = ffma2(make_float2(wv.x, wv.y), make_float2(pv[i].x, pv[i].y), s);
            s = ffma2(make_float2(wv.z, wv.w), make_float2(pv[i].z, pv[i].w), s);
        }
        float t = s.x + s.y;
        #pragma unroll
        for (int off = 16; off > 0; off >>= 1)
            t += __shfl_xor_sync(0xffffffffu, t, off);
        if (lane == j0) my = t;
    }

    if (lane < 8) {
        int j = jg * 8 + lane;
        out[(long)r * D_ + j] = b_out[j] + my;
    }
}

// ======================================================================
extern "C" void kernel_launch(void* const* d_in, const int* in_sizes, int n_in,
                              void* d_out, int out_size)
{
    const float* x       = (const float*)d_in[0];
    const int*   mask    = (const int*)  d_in[1];
    const float* queries = (const float*)d_in[2];
    const float* w_out   = (const float*)d_in[3];
    const float* b_out   = (const float*)d_in[4];
    float* out = (float*)d_out;

    cudaFuncSetAttribute((const void*)attn_main,
                         cudaFuncAttributeMaxDynamicSharedMemorySize, SMEM_BYTES);

    // zero the atomic accumulators via graph memset nodes
    void* p_pool = nullptr; void* p_lsum = nullptr;
    cudaGetSymbolAddress(&p_pool, g_pool);
    cudaGetSymbolAddress(&p_lsum, g_lsum);
    cudaMemsetAsync(p_pool, 0, sizeof(float) * B_ * K_ * D_);
    cudaMemsetAsync(p_lsum, 0, sizeof(float) * B_ * K_ * H_);

    attn_main<<<G_, NTHR_, SMEM_BYTES>>>(x, mask, queries);
    epi_k<<<512, 256>>>(w_out, b_out, out);
}